// round 2
// baseline (speedup 1.0000x reference)
#include <cuda_runtime.h>

// enc_mtan_classif: the reference's attention softmax is over a broadcast-constant
// logit (scores depend only on (b,q) along the softmax axis t), so attention
// weights are exactly uniform over mask-valid timesteps:
//   att[b,q,c] = masked mean over t of x[b,t,c]   (independent of q)
// => all LQ GRU inputs are identical; gi = W_ih@a + b_ih computed once.
// Whole net: masked-mean -> Wo -> (W_ih once) -> 128-step GRU recurrence -> MLP.
// One CTA per batch (128 CTAs = single wave), 384 threads; thread j owns row j
// of W_hh in registers; h broadcast from smem via float4 (bank-broadcast).

__device__ __forceinline__ float sigmoidf_(float v) {
    return 1.0f / (1.0f + expf(-v));
}

__global__ void __launch_bounds__(384, 1)
mtan_fused_kernel(const float* __restrict__ x,
                  const float* __restrict__ Wo,  const float* __restrict__ bo,
                  const float* __restrict__ Wih, const float* __restrict__ Whh,
                  const float* __restrict__ bih, const float* __restrict__ bhh,
                  const float* __restrict__ W1,  const float* __restrict__ b1,
                  const float* __restrict__ W2,  const float* __restrict__ b2,
                  const float* __restrict__ W3,  const float* __restrict__ b3,
                  float* __restrict__ out)
{
    __shared__ __align__(16) float s_h[128];
    __shared__ float s_gh[384];
    __shared__ float s_gi[384];
    __shared__ float s_att[32];
    __shared__ __align__(16) float s_a[128];
    __shared__ __align__(16) float s_o1[304];
    __shared__ __align__(16) float s_o2[304];
    __shared__ float ps[12][32];
    __shared__ float pf[12][32];
    __shared__ float pc[12][32];

    const int b = blockIdx.x;
    const int j = threadIdx.x;
    const float* xb = x + (size_t)b * 128 * 32;

    // ---------- Phase 1: att[c] = masked mean over t (uniform softmax) ----------
    {
        const int c = j & 31;           // channel 0..31 of (values||mask)
        const int g = j >> 5;           // warp/group 0..11
        const int mc = 16 + (c & 15);   // this channel's mask slot
        float sm = 0.0f, fs = 0.0f, cn = 0.0f;
        for (int t = g; t < 128; t += 12) {
            float xv = xb[t * 32 + c];
            float mv = xb[t * 32 + mc];   // exactly 0.0 or 1.0
            fs += xv;
            sm += xv * mv;
            cn += mv;
        }
        ps[g][c] = sm; pf[g][c] = fs; pc[g][c] = cn;
    }
    __syncthreads();
    if (j < 32) {
        float S = 0.0f, F = 0.0f, C = 0.0f;
        #pragma unroll
        for (int g = 0; g < 12; g++) { S += ps[g][j]; F += pf[g][j]; C += pc[g][j]; }
        // valid positions exist: uniform over valid; none: all logits -1e9 -> uniform over T
        s_att[j] = (C > 0.0f) ? (S / C) : (F * (1.0f / 128.0f));
    }
    __syncthreads();

    // ---------- Phase 2: a = Wo @ att + bo  (128x32 matvec) ----------
    if (j < 128) {
        const float4* wr = (const float4*)(Wo + j * 32);
        const float4* a4 = (const float4*)s_att;
        float acc = bo[j];
        #pragma unroll
        for (int k = 0; k < 8; k++) {
            float4 w4 = wr[k];
            float4 av = a4[k];
            acc += w4.x * av.x + w4.y * av.y + w4.z * av.z + w4.w * av.w;
        }
        s_a[j] = acc;
    }
    __syncthreads();

    // ---------- Phase 3: gi = W_ih @ a + b_ih (once); stage W_hh row in regs ----
    float w[128];
    float bhh_j;
    {
        const float4* wi = (const float4*)(Wih + (size_t)j * 128);
        const float4* wh = (const float4*)(Whh + (size_t)j * 128);
        const float4* a4 = (const float4*)s_a;
        float acc = bih[j];
        #pragma unroll
        for (int k = 0; k < 32; k++) {
            float4 w4 = wi[k];
            float4 av = a4[k];
            acc += w4.x * av.x + w4.y * av.y + w4.z * av.z + w4.w * av.w;
            float4 h4 = wh[k];
            w[4*k+0] = h4.x; w[4*k+1] = h4.y; w[4*k+2] = h4.z; w[4*k+3] = h4.w;
        }
        s_gi[j] = acc;
        bhh_j = bhh[j];
    }
    if (j < 128) s_h[j] = 0.0f;
    __syncthreads();

    // ---------- Phase 4: GRU, 128 steps, constant input ----------
    // Per step/thread: 128 FMAs vs 32 broadcast LDS.128 -> FMA-pipe bound.
    float h_j = 0.0f;
    const float4* h4p = (const float4*)s_h;
    for (int step = 0; step < 128; step++) {
        float a0 = bhh_j, a1 = 0.0f;     // 2 accumulators, 2 live float4 temps
        #pragma unroll
        for (int k = 0; k < 32; k += 2) {
            float4 v0 = h4p[k + 0];
            a0 += w[4*k+0]*v0.x + w[4*k+1]*v0.y + w[4*k+2]*v0.z + w[4*k+3]*v0.w;
            float4 v1 = h4p[k + 1];
            a1 += w[4*k+4]*v1.x + w[4*k+5]*v1.y + w[4*k+6]*v1.z + w[4*k+7]*v1.w;
        }
        s_gh[j] = a0 + a1;
        __syncthreads();
        if (j < 128) {
            float r = sigmoidf_(s_gi[j]       + s_gh[j]);
            float z = sigmoidf_(s_gi[j + 128] + s_gh[j + 128]);
            float n = tanhf(s_gi[j + 256] + r * s_gh[j + 256]);
            h_j = (1.0f - z) * n + z * h_j;
            s_h[j] = h_j;
        }
        __syncthreads();
    }

    // ---------- Phase 5: MLP 128 -> 300 -> 300 -> 2 ----------
    if (j < 300) {
        const float4* wr = (const float4*)(W1 + (size_t)j * 128);
        float acc = b1[j];
        #pragma unroll
        for (int k = 0; k < 32; k++) {
            float4 wv = wr[k];
            float4 hv = h4p[k];
            acc += wv.x * hv.x + wv.y * hv.y + wv.z * hv.z + wv.w * hv.w;
        }
        s_o1[j] = fmaxf(acc, 0.0f);
    }
    __syncthreads();
    if (j < 300) {
        // row stride 300 floats = 1200 B -> 16B aligned, 75 float4 per row
        const float4* wr = (const float4*)(W2 + (size_t)j * 300);
        const float4* o4 = (const float4*)s_o1;
        float acc = b2[j];
        #pragma unroll 15
        for (int k = 0; k < 75; k++) {
            float4 wv = wr[k];
            float4 ov = o4[k];
            acc += wv.x * ov.x + wv.y * ov.y + wv.z * ov.z + wv.w * ov.w;
        }
        s_o2[j] = fmaxf(acc, 0.0f);
    }
    __syncthreads();
    if (j < 64) {
        const int o    = j >> 5;   // output 0 or 1, one full warp each
        const int lane = j & 31;
        const float* w3 = W3 + o * 300;
        float acc = 0.0f;
        for (int k = lane; k < 300; k += 32) acc += w3[k] * s_o2[k];
        #pragma unroll
        for (int off = 16; off; off >>= 1)
            acc += __shfl_down_sync(0xffffffffu, acc, off);
        if (lane == 0) out[b * 2 + o] = acc + b3[o];
    }
}

extern "C" void kernel_launch(void* const* d_in, const int* in_sizes, int n_in,
                              void* d_out, int out_size)
{
    // metadata order:
    // 0 x, 1 query_p, 2 W_per, 3 b_per, 4 W_lin, 5 b_lin, 6 Wq, 7 bq, 8 Wk, 9 bk,
    // 10 Wo, 11 bo, 12 W_ih, 13 W_hh, 14 b_ih, 15 b_hh,
    // 16 W1, 17 b1, 18 W2, 19 b2, 20 W3, 21 b3
    // (1..9 are provably dead under the uniform-softmax identity)
    const float* x   = (const float*)d_in[0];
    const float* Wo  = (const float*)d_in[10];
    const float* bo  = (const float*)d_in[11];
    const float* Wih = (const float*)d_in[12];
    const float* Whh = (const float*)d_in[13];
    const float* bih = (const float*)d_in[14];
    const float* bhh = (const float*)d_in[15];
    const float* W1  = (const float*)d_in[16];
    const float* b1  = (const float*)d_in[17];
    const float* W2  = (const float*)d_in[18];
    const float* b2  = (const float*)d_in[19];
    const float* W3  = (const float*)d_in[20];
    const float* b3  = (const float*)d_in[21];
    float* out = (float*)d_out;

    mtan_fused_kernel<<<128, 384>>>(x, Wo, bo, Wih, Whh, bih, bhh,
                                    W1, b1, W2, b2, W3, b3, out);
}

// round 4
// speedup vs baseline: 1.1885x; 1.1885x over previous
#include <cuda_runtime.h>

// enc_mtan_classif: the reference's attention softmax is over a broadcast-constant
// logit along the softmax axis, so attention weights are exactly uniform over
// mask-valid timesteps:
//   att[b,c] = masked mean over t of x[b,t,c]   (independent of q, h)
// => all LQ GRU inputs identical; gi = W_ih@a + b_ih computed once.
// Net: masked-mean -> Wo -> (W_ih once) -> 128-step GRU recurrence -> MLP.
// One CTA per batch, 384 threads; thread j owns row j of W_hh packed as 64
// f32x2 pairs in registers; h broadcast from smem via float4.
// R3/R4: packed dual-FP32 fma.rn.f32x2 (FFMA2) + MUFU-based fast sigmoid/tanh.
// (Resubmission: R3 never ran — broker timeout.)

__device__ __forceinline__ unsigned long long pk2(float lo, float hi) {
    unsigned long long r;
    asm("mov.b64 %0, {%1, %2};" : "=l"(r) : "f"(lo), "f"(hi));
    return r;
}
__device__ __forceinline__ void upk2(unsigned long long v, float& lo, float& hi) {
    asm("mov.b64 {%0, %1}, %2;" : "=f"(lo), "=f"(hi) : "l"(v));
}
__device__ __forceinline__ unsigned long long ffma2(unsigned long long a,
                                                    unsigned long long b,
                                                    unsigned long long c) {
    unsigned long long d;
    asm("fma.rn.f32x2 %0, %1, %2, %3;" : "=l"(d) : "l"(a), "l"(b), "l"(c));
    return d;
}

// MUFU-based fast sigmoid / tanh (err ~1e-6, clamped so __expf never overflows)
__device__ __forceinline__ float fsig(float v) {
    v = fminf(fmaxf(v, -30.0f), 30.0f);
    return __fdividef(1.0f, 1.0f + __expf(-v));
}
__device__ __forceinline__ float ftanh(float v) {
    v = fminf(fmaxf(v, -15.0f), 15.0f);
    float t = __expf(2.0f * v);
    return __fdividef(t - 1.0f, t + 1.0f);
}

__global__ void __launch_bounds__(384, 1)
mtan_fused_kernel(const float* __restrict__ x,
                  const float* __restrict__ Wo,  const float* __restrict__ bo,
                  const float* __restrict__ Wih, const float* __restrict__ Whh,
                  const float* __restrict__ bih, const float* __restrict__ bhh,
                  const float* __restrict__ W1,  const float* __restrict__ b1,
                  const float* __restrict__ W2,  const float* __restrict__ b2,
                  const float* __restrict__ W3,  const float* __restrict__ b3,
                  float* __restrict__ out)
{
    __shared__ __align__(16) float s_h[128];
    __shared__ float s_gh[384];
    __shared__ float s_gi[384];
    __shared__ __align__(16) float s_att[32];
    __shared__ __align__(16) float s_a[128];
    __shared__ __align__(16) float s_o1[304];
    __shared__ __align__(16) float s_o2[304];
    __shared__ float ps[12][32];
    __shared__ float pf[12][32];
    __shared__ float pc[12][32];

    const int b = blockIdx.x;
    const int j = threadIdx.x;
    const float* xb = x + (size_t)b * 128 * 32;

    // ---------- Phase 1: att[c] = masked mean over t (uniform softmax) ----------
    {
        const int c = j & 31;           // channel 0..31 of (values||mask)
        const int g = j >> 5;           // warp 0..11
        const int mc = 16 + (c & 15);   // this channel's mask slot
        float sm = 0.0f, fs = 0.0f, cn = 0.0f;
        for (int t = g; t < 128; t += 12) {
            float xv = xb[t * 32 + c];
            float mv = xb[t * 32 + mc];   // exactly 0.0 or 1.0
            fs += xv;
            sm += xv * mv;
            cn += mv;
        }
        ps[g][c] = sm; pf[g][c] = fs; pc[g][c] = cn;
    }
    __syncthreads();
    if (j < 32) {
        float S = 0.0f, F = 0.0f, C = 0.0f;
        #pragma unroll
        for (int g = 0; g < 12; g++) { S += ps[g][j]; F += pf[g][j]; C += pc[g][j]; }
        s_att[j] = (C > 0.0f) ? __fdividef(S, C) : (F * (1.0f / 128.0f));
    }
    __syncthreads();

    // ---------- Phase 2: a = Wo @ att + bo  (128x32 matvec) ----------
    if (j < 128) {
        const float4* wr = (const float4*)(Wo + j * 32);
        const float4* a4 = (const float4*)s_att;
        float acc = bo[j];
        #pragma unroll
        for (int k = 0; k < 8; k++) {
            float4 w4 = wr[k];
            float4 av = a4[k];
            acc += w4.x * av.x + w4.y * av.y + w4.z * av.z + w4.w * av.w;
        }
        s_a[j] = acc;
    }
    __syncthreads();

    // ---------- Phase 3: gi = W_ih @ a + b_ih (once); pack W_hh row in regs ----
    unsigned long long w2[64];   // row j of W_hh as 64 f32x2 pairs (128 regs)
    float bhh_j;
    {
        const float4* wi = (const float4*)(Wih + (size_t)j * 128);
        const float4* wh = (const float4*)(Whh + (size_t)j * 128);
        const float4* a4 = (const float4*)s_a;
        float acc = bih[j];
        #pragma unroll
        for (int k = 0; k < 32; k++) {
            float4 w4 = wi[k];
            float4 av = a4[k];
            acc += w4.x * av.x + w4.y * av.y + w4.z * av.z + w4.w * av.w;
            float4 h4 = wh[k];
            w2[2*k]   = pk2(h4.x, h4.y);
            w2[2*k+1] = pk2(h4.z, h4.w);
        }
        s_gi[j] = acc;
        bhh_j = bhh[j];
    }
    if (j < 128) s_h[j] = 0.0f;
    __syncthreads();

    // ---------- Phase 4: GRU, 128 steps, constant input ----------
    // Per thread-step: 32 broadcast LDS.128 + 64 FFMA2 (dual-FP32 pipe).
    float h_j = 0.0f;
    const float4* h4p = (const float4*)s_h;
    for (int step = 0; step < 128; step++) {
        unsigned long long acc0 = pk2(bhh_j, 0.0f);
        unsigned long long acc1 = 0ull;   // (0.0f, 0.0f)
        #pragma unroll
        for (int k = 0; k < 32; k++) {
            float4 v = h4p[k];
            acc0 = ffma2(w2[2*k],   pk2(v.x, v.y), acc0);
            acc1 = ffma2(w2[2*k+1], pk2(v.z, v.w), acc1);
        }
        float e0, e1, e2, e3;
        upk2(acc0, e0, e1); upk2(acc1, e2, e3);
        s_gh[j] = (e0 + e2) + (e1 + e3);
        __syncthreads();
        if (j < 128) {
            float r = fsig(s_gi[j]       + s_gh[j]);
            float z = fsig(s_gi[j + 128] + s_gh[j + 128]);
            float n = ftanh(s_gi[j + 256] + r * s_gh[j + 256]);
            h_j = (1.0f - z) * n + z * h_j;
            s_h[j] = h_j;
        }
        __syncthreads();
    }

    // ---------- Phase 5: MLP 128 -> 300 -> 300 -> 2 ----------
    if (j < 300) {
        const float4* wr = (const float4*)(W1 + (size_t)j * 128);
        unsigned long long a0 = 0ull, a1 = 0ull;
        #pragma unroll
        for (int k = 0; k < 32; k++) {
            float4 wv = wr[k];
            float4 hv = h4p[k];
            a0 = ffma2(pk2(wv.x, wv.y), pk2(hv.x, hv.y), a0);
            a1 = ffma2(pk2(wv.z, wv.w), pk2(hv.z, hv.w), a1);
        }
        float e0, e1, e2, e3;
        upk2(a0, e0, e1); upk2(a1, e2, e3);
        s_o1[j] = fmaxf(b1[j] + (e0 + e2) + (e1 + e3), 0.0f);
    }
    __syncthreads();
    if (j < 300) {
        // row stride 300 floats = 1200 B -> 16B aligned, 75 float4 per row
        const float4* wr = (const float4*)(W2 + (size_t)j * 300);
        const float4* o4 = (const float4*)s_o1;
        unsigned long long a0 = 0ull, a1 = 0ull;
        #pragma unroll 15
        for (int k = 0; k < 75; k++) {
            float4 wv = wr[k];
            float4 ov = o4[k];
            a0 = ffma2(pk2(wv.x, wv.y), pk2(ov.x, ov.y), a0);
            a1 = ffma2(pk2(wv.z, wv.w), pk2(ov.z, ov.w), a1);
        }
        float e0, e1, e2, e3;
        upk2(a0, e0, e1); upk2(a1, e2, e3);
        s_o2[j] = fmaxf(b2[j] + (e0 + e2) + (e1 + e3), 0.0f);
    }
    __syncthreads();
    if (j < 64) {
        const int o    = j >> 5;   // output 0 or 1, one full warp each
        const int lane = j & 31;
        const float* w3 = W3 + o * 300;
        float acc = 0.0f;
        for (int k = lane; k < 300; k += 32) acc += w3[k] * s_o2[k];
        #pragma unroll
        for (int off = 16; off; off >>= 1)
            acc += __shfl_down_sync(0xffffffffu, acc, off);
        if (lane == 0) out[b * 2 + o] = acc + b3[o];
    }
}

extern "C" void kernel_launch(void* const* d_in, const int* in_sizes, int n_in,
                              void* d_out, int out_size)
{
    // metadata order:
    // 0 x, 1 query_p, 2 W_per, 3 b_per, 4 W_lin, 5 b_lin, 6 Wq, 7 bq, 8 Wk, 9 bk,
    // 10 Wo, 11 bo, 12 W_ih, 13 W_hh, 14 b_ih, 15 b_hh,
    // 16 W1, 17 b1, 18 W2, 19 b2, 20 W3, 21 b3
    // (1..9 are provably dead under the uniform-softmax identity)
    const float* x   = (const float*)d_in[0];
    const float* Wo  = (const float*)d_in[10];
    const float* bo  = (const float*)d_in[11];
    const float* Wih = (const float*)d_in[12];
    const float* Whh = (const float*)d_in[13];
    const float* bih = (const float*)d_in[14];
    const float* bhh = (const float*)d_in[15];
    const float* W1  = (const float*)d_in[16];
    const float* b1  = (const float*)d_in[17];
    const float* W2  = (const float*)d_in[18];
    const float* b2  = (const float*)d_in[19];
    const float* W3  = (const float*)d_in[20];
    const float* b3  = (const float*)d_in[21];
    float* out = (float*)d_out;

    mtan_fused_kernel<<<128, 384>>>(x, Wo, bo, Wih, Whh, bih, bhh,
                                    W1, b1, W2, b2, W3, b3, out);
}